// round 12
// baseline (speedup 1.0000x reference)
#include <cuda_runtime.h>
#include <math.h>

// RBFSolver: out[0,f,t] = sum_k w_k / (1 + 4pi^2 ex^2)
//            out[1,f,t] = -2pi sum_k w_k ex / (1 + 4pi^2 ex^2)
// ex = exp(log f + log t + y_k), y = linspace(-50,50,500), w_k = exp(-y_k^2)*dy.
//
// The reference's Riemann sum equals int e^{-y^2} g(s+y) dy to ~1e-21; g is
// analytic in |Im y| < pi/2, so 8-point GAUSS-HERMITE reproduces it to
// ~8e-5 relative (measured R9-R11) vs tolerance 1e-3.
//
// R12: kernel time is ramp-dominated (R10 vs R11: 2x work change -> same
// time). Minimize CTA dispatch events: 4 outputs/thread, 32768 threads as
// 128 CTAs x 256 -> 8x fewer CTAs than R10/R11, <=1 CTA/SM (zero tail
// imbalance), two independent f32x2 accumulator streams for ILP, and the
// epilogue collapses to two STG.128.
// Carried: no log (f*exp(lt)); -2pi folded into esc (d is sign-blind, im
// accumulator IS a_im); GH table by value, compile-time-indexed (uniform
// const reads only; divergent LDC fatal); batched rcp per 2-lane stream;
// single launch.

#define GH_N    8
#define F_DIM   512
#define T_DIM   256
#define BLK     256
#define NBLK    (F_DIM * T_DIM / 4 / BLK)   // 128

typedef unsigned long long u64;

#define MUL2(o,a,b)   asm("mul.rn.f32x2 %0, %1, %2;"     : "=l"(o) : "l"(a), "l"(b))
#define ADD2(o,a,b)   asm("add.rn.f32x2 %0, %1, %2;"     : "=l"(o) : "l"(a), "l"(b))
#define FMA2(o,a,b,c) asm("fma.rn.f32x2 %0, %1, %2, %3;" : "=l"(o) : "l"(a), "l"(b), "l"(c))
#define PACK2(o,lo,hi)   asm("mov.b64 %0, {%1, %2};" : "=l"(o) : "f"(lo), "f"(hi))
#define UNPACK2(lo,hi,i) asm("mov.b64 {%0, %1}, %2;" : "=f"(lo), "=f"(hi) : "l"(i))
#define RCPA(o,a)     asm("rcp.approx.ftz.f32 %0, %1;" : "=f"(o) : "f"(a))

struct QuadTbl {
    float2 p[GH_N];     // (E_i = exp(node_i), w_i)
};

__global__ __launch_bounds__(BLK)
void rbf_solver_kernel(const float* __restrict__ f_vec,
                       const float* __restrict__ log_t_vec,
                       float* __restrict__ out,
                       const QuadTbl tbl)
{
    const int gid = blockIdx.x * BLK + threadIdx.x;   // 0..32767
    const int f   = gid >> 6;            // 0..511, uniform per block
    const int tq  = gid & 63;            // t-quad index; t = 4*tq .. 4*tq+3

    // esc = -2pi * f * exp(log t); d = fma(exF,exF,1) is sign-invariant,
    // so the im accumulator comes out as a_im directly.
    const float  c  = -6.283185307179586f * f_vec[f];
    const float4 lt = ((const float4*)log_t_vec)[tq];     // LDG.128
    const float  e0 = c * __expf(lt.x);
    const float  e1 = c * __expf(lt.y);
    const float  e2 = c * __expf(lt.z);
    const float  e3 = c * __expf(lt.w);

    u64 escA, escB, one2, reA, reB, imA, imB;
    PACK2(escA, e0, e1);
    PACK2(escB, e2, e3);
    {
        float one = 1.0f, zero = 0.0f;
        PACK2(one2, one, one);
        PACK2(reA, zero, zero);  PACK2(reB, zero, zero);
        PACK2(imA, zero, zero);  PACK2(imB, zero, zero);
    }

    #pragma unroll
    for (int i = 0; i < GH_N; ++i) {
        float2 v = tbl.p[i];                 // uniform const-bank read
        u64 E2, w2;
        PACK2(E2, v.x, v.x);
        PACK2(w2, v.y, v.y);

        // Stream A (t lanes 0,1) and stream B (t lanes 2,3): independent.
        u64 exFA;  MUL2(exFA, escA, E2);
        u64 exFB;  MUL2(exFB, escB, E2);
        u64 dA;    FMA2(dA, exFA, exFA, one2);
        u64 dB;    FMA2(dB, exFB, exFB, one2);

        float a0, a1, b0, b1;
        UNPACK2(a0, a1, dA);
        UNPACK2(b0, b1, dB);
        float pA = a0 * a1;                 // <= ~2e15, rcp-safe
        float pB = b0 * b1;
        float rA; RCPA(rA, pA);             // MUFU.RCP
        float rB; RCPA(rB, pB);             // MUFU.RCP
        u64 r2A;   PACK2(r2A, rA * a1, rA * a0);
        u64 r2B;   PACK2(r2B, rB * b1, rB * b0);

        u64 twA;   MUL2(twA, w2, r2A);
        u64 twB;   MUL2(twB, w2, r2B);
        ADD2(reA, reA, twA);
        ADD2(reB, reB, twB);
        FMA2(imA, twA, exFA, imA);
        FMA2(imB, twB, exFB, imB);
    }

    // 4 contiguous outputs per channel -> one STG.128 each.
    ulonglong2* o128 = (ulonglong2*)out;
    o128[gid]                       = make_ulonglong2(reA, reB);  // a_re
    o128[(F_DIM * T_DIM / 4) + gid] = make_ulonglong2(imA, imB);  // a_im
}

// ---------------------------------------------------------------------------
// Host: 8-point Gauss-Hermite nodes/weights (physicists' H_8), computed in
// double via sign-scan + bisection. Input-independent; runs at capture time.
// ---------------------------------------------------------------------------
static double hermite_H(int n, double x)
{
    double h0 = 1.0, h1 = 2.0 * x;
    for (int k = 1; k < n; ++k) {
        double h2 = 2.0 * x * h1 - 2.0 * (double)k * h0;
        h0 = h1; h1 = h2;
    }
    return h1;
}

extern "C" void kernel_launch(void* const* d_in, const int* in_sizes, int n_in,
                              void* d_out, int out_size)
{
    const float* f_vec     = (const float*)d_in[0];   // (512,)
    const float* log_t_vec = (const float*)d_in[1];   // (256,)
    float* out             = (float*)d_out;           // (2, 512, 256)

    (void)in_sizes; (void)n_in; (void)out_size;

    // Positive roots of H_8 by scan + bisection on (0, 4).
    double xr[GH_N];      // all 8 nodes, ascending
    double wt[GH_N];
    {
        double roots[GH_N / 2];
        int nr = 0;
        double step = 1e-3;
        double prev = hermite_H(GH_N, 1e-12);
        for (double x = step; x < 4.0 && nr < GH_N / 2; x += step) {
            double cur = hermite_H(GH_N, x);
            if (prev * cur < 0.0) {
                double lo = x - step, hi = x;
                for (int it = 0; it < 80; ++it) {
                    double mid = 0.5 * (lo + hi);
                    double fm = hermite_H(GH_N, mid);
                    if (fm * prev <= 0.0) hi = mid; else lo = mid;
                }
                roots[nr++] = 0.5 * (lo + hi);
            }
            prev = cur;
        }
        // weights: w_i = 2^{n-1} n! sqrt(pi) / (n^2 * H_{n-1}(x_i)^2)
        double fact = 1.0;
        for (int k = 2; k <= GH_N; ++k) fact *= (double)k;
        const double wnum = ldexp(1.0, GH_N - 1) * fact * sqrt(3.14159265358979323846)
                            / ((double)GH_N * (double)GH_N);
        for (int i = 0; i < GH_N / 2; ++i) {
            double hm = hermite_H(GH_N - 1, roots[i]);
            double w  = wnum / (hm * hm);
            xr[GH_N / 2 + i]     =  roots[i];
            xr[GH_N / 2 - 1 - i] = -roots[i];
            wt[GH_N / 2 + i]     = w;
            wt[GH_N / 2 - 1 - i] = w;
        }
    }

    QuadTbl tbl;
    for (int i = 0; i < GH_N; ++i)
        tbl.p[i] = make_float2((float)exp(xr[i]), (float)wt[i]);

    rbf_solver_kernel<<<NBLK, BLK>>>(f_vec, log_t_vec, out, tbl);
}